// round 9
// baseline (speedup 1.0000x reference)
#include <cuda_runtime.h>

#define N_  256
#define P_  5
#define H_  32
#define B_  256
#define K_  1280            // N_*P_
#define THRESH_ 0.01f

#define SPLITK 32
#define JC 8                // j per chunk
#define KC 40               // K per chunk = JC*P_
#define BSP 68              // padded Bs row (17*16B -> rows stay 16B aligned)

// ---- scratch ----
__device__ float g_part[SPLITK][B_ * N_]; // split-K partials [z][b][i]

#define FMA_F32X2(d, a, b) \
    asm("fma.rn.f32x2 %0, %1, %2, %0;" : "+l"(d) : "l"(a), "l"(b))

// ---------------------------------------------------------------
// Fused GEMM with packed f32x2 FMA.
// grid = (4 i-tiles, 4 b-tiles, 32 k-chunks) = 512 blocks, 256 thr.
// ---------------------------------------------------------------
__global__ __launch_bounds__(256)
void gemm_fused(const float* __restrict__ x,
                const float* __restrict__ adj,
                const float* __restrict__ bp,
                const float* __restrict__ w_pw,
                const float* __restrict__ b_pw)
{
    __shared__ __align__(16) float As2[KC][128];   // act duplicated: [k][2b]=(v,v)
    __shared__ __align__(16) float Bs[KC][BSP];    // effw: [k][i]
    __shared__ float adj_s[JC][64];                // masked adjacency.T chunk [j][i]
    __shared__ float bp_s[KC];
    __shared__ float bsum[4][64];                  // bias chunk partials

    const int tid = threadIdx.x;
    const int i0  = blockIdx.x * 64;
    const int b0  = blockIdx.y * 64;
    const int j0  = blockIdx.z * JC;
    const int kc0 = j0 * P_;

    // ---- stage bp chunk + masked adj chunk ----
    if (tid < KC) bp_s[tid] = bp[kc0 + tid];
    if (tid < 128) {
        const int j  = tid >> 4;          // 0..7
        const int i4 = (tid & 15) * 4;
        float4 e = *reinterpret_cast<const float4*>(adj + (size_t)(j0 + j) * N_ + i0 + i4);
        const int gj = j0 + j;
        adj_s[j][i4 + 0] = (e.x > THRESH_ && (i0 + i4 + 0) != gj) ? e.x : 0.f;
        adj_s[j][i4 + 1] = (e.y > THRESH_ && (i0 + i4 + 1) != gj) ? e.y : 0.f;
        adj_s[j][i4 + 2] = (e.z > THRESH_ && (i0 + i4 + 2) != gj) ? e.z : 0.f;
        adj_s[j][i4 + 3] = (e.w > THRESH_ && (i0 + i4 + 3) != gj) ? e.w : 0.f;
    }
    __syncthreads();

    // ---- generate effw tile: Bs[k][i] = adj_s[j(k)][i] * w_pw[i][k] ----
    {
        const int r = tid >> 2;           // i-local 0..63
        const int q = tid & 3;
        #pragma unroll
        for (int c = 0; c < 3; ++c) {
            const int f4 = (c < 2) ? (c * 4 + q) : (8 + q);   // float4 index 0..9
            if (c < 2 || q < 2) {
                const int kq = f4 * 4;
                float4 w = *reinterpret_cast<const float4*>(
                    w_pw + (size_t)(i0 + r) * K_ + kc0 + kq);
                Bs[kq + 0][r] = adj_s[(kq + 0) / P_][r] * w.x;
                Bs[kq + 1][r] = adj_s[(kq + 1) / P_][r] * w.y;
                Bs[kq + 2][r] = adj_s[(kq + 2) / P_][r] * w.z;
                Bs[kq + 3][r] = adj_s[(kq + 3) / P_][r] * w.w;
            }
        }
    }
    // ---- generate duplicated act tile: As2[k][2b..2b+1] = (relu, relu) ----
    {
        const int r  = tid & 63;          // b-local
        const int qq = tid >> 6;          // 0..3 -> 2 j each
        float2 xv = *reinterpret_cast<const float2*>(
            x + (size_t)(b0 + r) * N_ + j0 + qq * 2);
        float xl[2] = {xv.x, xv.y};
        #pragma unroll
        for (int jj = 0; jj < 2; ++jj) {
            const int jl = qq * 2 + jj;
            #pragma unroll
            for (int p = 0; p < P_; ++p) {
                const int k = jl * P_ + p;
                float v = fmaxf(xl[jj] - bp_s[k], 0.f);
                *reinterpret_cast<float2*>(&As2[k][2 * r]) = make_float2(v, v);
            }
        }
    }
    // ---- bias chunk partials ----
    {
        const int il = tid & 63;
        const int qq = tid >> 6;
        float2 bpv = *reinterpret_cast<const float2*>(
            b_pw + (size_t)(i0 + il) * N_ + j0 + qq * 2);
        float s = adj_s[qq * 2 + 0][il] * bpv.x;
        s = fmaf(adj_s[qq * 2 + 1][il], bpv.y, s);
        bsum[qq][il] = s;
    }
    __syncthreads();

    // ---- main loop: 4x4 tile as 4x(2x f32x2), 8 FMA2 per k ----
    const int tx = tid & 15;   // i direction
    const int ty = tid >> 4;   // b direction
    unsigned long long acc2[4][2] = {};

    #pragma unroll 8
    for (int k = 0; k < KC; ++k) {
        ulonglong2 bv = *reinterpret_cast<const ulonglong2*>(&Bs[k][tx * 4]);
        #pragma unroll
        for (int u = 0; u < 4; ++u) {
            unsigned long long av = *reinterpret_cast<const unsigned long long*>(
                &As2[k][2 * (ty * 4 + u)]);
            FMA_F32X2(acc2[u][0], av, bv.x);
            FMA_F32X2(acc2[u][1], av, bv.y);
        }
    }

    // ---- unpack, add bias chunk, store partials ----
    float bs0 = bsum[0][tx * 4 + 0] + bsum[1][tx * 4 + 0] + bsum[2][tx * 4 + 0] + bsum[3][tx * 4 + 0];
    float bs1 = bsum[0][tx * 4 + 1] + bsum[1][tx * 4 + 1] + bsum[2][tx * 4 + 1] + bsum[3][tx * 4 + 1];
    float bs2 = bsum[0][tx * 4 + 2] + bsum[1][tx * 4 + 2] + bsum[2][tx * 4 + 2] + bsum[3][tx * 4 + 2];
    float bs3 = bsum[0][tx * 4 + 3] + bsum[1][tx * 4 + 3] + bsum[2][tx * 4 + 3] + bsum[3][tx * 4 + 3];

    float* dst = g_part[blockIdx.z];
    #pragma unroll
    for (int u = 0; u < 4; ++u) {
        unsigned int c0, c1, c2, c3;
        asm("mov.b64 {%0, %1}, %2;" : "=r"(c0), "=r"(c1) : "l"(acc2[u][0]));
        asm("mov.b64 {%0, %1}, %2;" : "=r"(c2), "=r"(c3) : "l"(acc2[u][1]));
        float4 v = make_float4(__uint_as_float(c0) + bs0,
                               __uint_as_float(c1) + bs1,
                               __uint_as_float(c2) + bs2,
                               __uint_as_float(c3) + bs3);
        *reinterpret_cast<float4*>(&dst[(size_t)(b0 + ty * 4 + u) * N_ + i0 + tx * 4]) = v;
    }
}

// ---------------------------------------------------------------
// epilogue: grid = (8 i-tiles, 32 b-tiles) = 256 blocks, 256 thr.
// ---------------------------------------------------------------
#define EIT 32   // i per epi block
#define EBT 8    // b per epi block

__global__ __launch_bounds__(256)
void epi_kernel(const float* __restrict__ W1,
                const float* __restrict__ b1,
                const float* __restrict__ W2,
                const float* __restrict__ b2,
                float* __restrict__ out)
{
    __shared__ float w1s[H_][EIT + 1];
    __shared__ float b1s[H_][EIT + 1];
    __shared__ float w2m[H_][EIT + 1];
    __shared__ float w2s[H_][EIT + 1];
    __shared__ float b2s[2][EIT];

    const int tid = threadIdx.x;
    const int i0  = blockIdx.x * EIT;
    const int b0  = blockIdx.y * EBT;

    // ---- stage weights, coalesced ----
    {
        const int il = tid >> 5;
        const int k  = tid & 31;
        #pragma unroll
        for (int r = 0; r < 4; ++r) {
            const int i = il + r * 8;
            w1s[k][i] = W1[(i0 + i) * H_ + k];
            b1s[k][i] = b1[(i0 + i) * H_ + k];
        }
        const int il2 = tid >> 6;
        const int o   = tid & 63;
        #pragma unroll
        for (int r = 0; r < 8; ++r) {
            const int i = il2 + r * 4;
            float v = W2[(i0 + i) * 2 * H_ + o];
            if (o < H_) w2m[o][i] = v;
            else        w2s[o - H_][i] = v;
        }
        if (tid < 2 * EIT) {
            const int i = tid >> 1;
            b2s[tid & 1][i] = b2[(i0 + i) * 2 + (tid & 1)];
        }
    }
    __syncthreads();

    const int il = tid & 31;
    const int bq = tid >> 5;
    const int gi = i0 + il;
    const int b  = b0 + bq;

    float c = 0.f;
    #pragma unroll
    for (int s = 0; s < SPLITK; ++s)
        c += g_part[s][(size_t)b * N_ + gi];

    float m  = b2s[0][il];
    float sd = b2s[1][il];
    #pragma unroll
    for (int k = 0; k < H_; ++k) {
        float h = fmaxf(fmaf(c, w1s[k][il], b1s[k][il]), 0.f);
        m  = fmaf(w2m[k][il], h, m);
        sd = fmaf(w2s[k][il], h, sd);
    }
    out[(size_t)b * N_ + gi]        = m;
    out[(size_t)(B_ + b) * N_ + gi] = sd;
}

extern "C" void kernel_launch(void* const* d_in, const int* in_sizes, int n_in,
                              void* d_out, int out_size)
{
    const float* x    = (const float*)d_in[0];
    const float* adj  = (const float*)d_in[1];
    const float* bp   = (const float*)d_in[2];
    const float* w_pw = (const float*)d_in[3];
    const float* b_pw = (const float*)d_in[4];
    const float* W1   = (const float*)d_in[5];
    const float* b1   = (const float*)d_in[6];
    const float* W2   = (const float*)d_in[7];
    const float* b2   = (const float*)d_in[8];
    float* out = (float*)d_out;

    gemm_fused<<<dim3(4, 4, SPLITK), 256>>>(x, adj, bp, w_pw, b_pw);
    epi_kernel<<<dim3(N_ / EIT, B_ / EBT), 256>>>(W1, b1, W2, b2, out);
}

// round 10
// speedup vs baseline: 1.2354x; 1.2354x over previous
#include <cuda_runtime.h>

#define N_  256
#define P_  5
#define H_  32
#define B_  256
#define K_  1280            // N_*P_
#define THRESH_ 0.01f

#define SPLITK 16
#define KC 80               // K per chunk = 16 j exactly
#define JC 16               // j per chunk
#define BSP 68              // padded Bs row (rows stay 16B aligned)

// ---- scratch ----
__device__ float g_part[SPLITK][B_ * N_]; // split-K partials [z][b][i]

#define FMA_F32X2(d, a, b) \
    asm("fma.rn.f32x2 %0, %1, %2, %0;" : "+l"(d) : "l"(a), "l"(b))

#define PACK_DUP(d, s) \
    asm("mov.b64 %0, {%1, %1};" : "=l"(d) : "r"(__float_as_uint(s)))

// ---------------------------------------------------------------
// Fused GEMM (R8 structure) with packed f32x2 FMA main loop.
// grid = (4 i-tiles, 4 b-tiles, 16 k-chunks) = 256 blocks, 256 thr.
// ---------------------------------------------------------------
__global__ __launch_bounds__(256)
void gemm_fused(const float* __restrict__ x,
                const float* __restrict__ adj,
                const float* __restrict__ bp,
                const float* __restrict__ w_pw,
                const float* __restrict__ b_pw)
{
    __shared__ __align__(16) float As[KC][64];    // act:  [k][b]
    __shared__ __align__(16) float Bs[KC][BSP];   // effw: [k][i]
    __shared__ float adj_s[JC][64];               // masked adjacency.T chunk [j][i]
    __shared__ float bp_s[KC];
    __shared__ float bsum[4][64];                 // bias chunk partials

    const int tid = threadIdx.x;
    const int i0  = blockIdx.x * 64;
    const int b0  = blockIdx.y * 64;
    const int j0  = blockIdx.z * JC;
    const int kc0 = j0 * P_;

    // ---- stage bp chunk + masked adj chunk ----
    if (tid < KC) bp_s[tid] = bp[kc0 + tid];
    {
        const int j  = tid >> 4;          // 0..15
        const int i4 = (tid & 15) * 4;
        float4 e = *reinterpret_cast<const float4*>(adj + (size_t)(j0 + j) * N_ + i0 + i4);
        const int gj = j0 + j;
        adj_s[j][i4 + 0] = (e.x > THRESH_ && (i0 + i4 + 0) != gj) ? e.x : 0.f;
        adj_s[j][i4 + 1] = (e.y > THRESH_ && (i0 + i4 + 1) != gj) ? e.y : 0.f;
        adj_s[j][i4 + 2] = (e.z > THRESH_ && (i0 + i4 + 2) != gj) ? e.z : 0.f;
        adj_s[j][i4 + 3] = (e.w > THRESH_ && (i0 + i4 + 3) != gj) ? e.w : 0.f;
    }
    __syncthreads();

    // ---- generate effw tile: Bs[k][i] = adj_s[j(k)][i] * w_pw[i][k] ----
    {
        const int r = tid >> 2;           // i-local 0..63
        const int q = tid & 3;
        #pragma unroll
        for (int c = 0; c < 5; ++c) {
            const int kq = c * 16 + q * 4;
            float4 w = *reinterpret_cast<const float4*>(
                w_pw + (size_t)(i0 + r) * K_ + kc0 + kq);
            Bs[kq + 0][r] = adj_s[(kq + 0) / P_][r] * w.x;
            Bs[kq + 1][r] = adj_s[(kq + 1) / P_][r] * w.y;
            Bs[kq + 2][r] = adj_s[(kq + 2) / P_][r] * w.z;
            Bs[kq + 3][r] = adj_s[(kq + 3) / P_][r] * w.w;
        }
    }
    // ---- generate act tile: As[k][b] = relu(x[b, j(k)] - bp[k]) ----
    {
        const int r = tid & 63;           // b-local
        const int q = tid >> 6;           // 0..3 -> 4 j each
        float4 xv = *reinterpret_cast<const float4*>(
            x + (size_t)(b0 + r) * N_ + j0 + q * 4);
        float xl[4] = {xv.x, xv.y, xv.z, xv.w};
        #pragma unroll
        for (int jj = 0; jj < 4; ++jj) {
            const float xj = xl[jj];
            const int jl = q * 4 + jj;
            #pragma unroll
            for (int p = 0; p < P_; ++p) {
                const int k = jl * P_ + p;
                As[k][r] = fmaxf(xj - bp_s[k], 0.f);
            }
        }
    }
    // ---- bias chunk partials ----
    {
        const int il = tid & 63;
        const int q  = tid >> 6;
        float4 bpv = *reinterpret_cast<const float4*>(
            b_pw + (size_t)(i0 + il) * N_ + j0 + q * 4);
        float s = adj_s[q * 4 + 0][il] * bpv.x;
        s = fmaf(adj_s[q * 4 + 1][il], bpv.y, s);
        s = fmaf(adj_s[q * 4 + 2][il], bpv.z, s);
        s = fmaf(adj_s[q * 4 + 3][il], bpv.w, s);
        bsum[q][il] = s;
    }
    __syncthreads();

    // ---- main loop: 4x4 tile via 8 FMA2 per k (packs on alu pipe) ----
    const int tx = tid & 15;   // i direction
    const int ty = tid >> 4;   // b direction
    unsigned long long acc2[4][2] = {};

    #pragma unroll 8
    for (int k = 0; k < KC; ++k) {
        float4 a4 = *reinterpret_cast<const float4*>(&As[k][ty * 4]);
        ulonglong2 bv = *reinterpret_cast<const ulonglong2*>(&Bs[k][tx * 4]);
        unsigned long long a0, a1, a2, a3;
        PACK_DUP(a0, a4.x);
        PACK_DUP(a1, a4.y);
        PACK_DUP(a2, a4.z);
        PACK_DUP(a3, a4.w);
        FMA_F32X2(acc2[0][0], a0, bv.x); FMA_F32X2(acc2[0][1], a0, bv.y);
        FMA_F32X2(acc2[1][0], a1, bv.x); FMA_F32X2(acc2[1][1], a1, bv.y);
        FMA_F32X2(acc2[2][0], a2, bv.x); FMA_F32X2(acc2[2][1], a2, bv.y);
        FMA_F32X2(acc2[3][0], a3, bv.x); FMA_F32X2(acc2[3][1], a3, bv.y);
    }

    // ---- unpack, add bias chunk, store partials ----
    float bs0 = bsum[0][tx * 4 + 0] + bsum[1][tx * 4 + 0] + bsum[2][tx * 4 + 0] + bsum[3][tx * 4 + 0];
    float bs1 = bsum[0][tx * 4 + 1] + bsum[1][tx * 4 + 1] + bsum[2][tx * 4 + 1] + bsum[3][tx * 4 + 1];
    float bs2 = bsum[0][tx * 4 + 2] + bsum[1][tx * 4 + 2] + bsum[2][tx * 4 + 2] + bsum[3][tx * 4 + 2];
    float bs3 = bsum[0][tx * 4 + 3] + bsum[1][tx * 4 + 3] + bsum[2][tx * 4 + 3] + bsum[3][tx * 4 + 3];

    float* dst = g_part[blockIdx.z];
    #pragma unroll
    for (int u = 0; u < 4; ++u) {
        unsigned int c0, c1, c2, c3;
        asm("mov.b64 {%0, %1}, %2;" : "=r"(c0), "=r"(c1) : "l"(acc2[u][0]));
        asm("mov.b64 {%0, %1}, %2;" : "=r"(c2), "=r"(c3) : "l"(acc2[u][1]));
        float4 v = make_float4(__uint_as_float(c0) + bs0,
                               __uint_as_float(c1) + bs1,
                               __uint_as_float(c2) + bs2,
                               __uint_as_float(c3) + bs3);
        *reinterpret_cast<float4*>(&dst[(size_t)(b0 + ty * 4 + u) * N_ + i0 + tx * 4]) = v;
    }
}

// ---------------------------------------------------------------
// epilogue: grid = (8 i-tiles, 32 b-tiles) = 256 blocks, 256 thr.
// ---------------------------------------------------------------
#define EIT 32   // i per epi block
#define EBT 8    // b per epi block

__global__ __launch_bounds__(256)
void epi_kernel(const float* __restrict__ W1,
                const float* __restrict__ b1,
                const float* __restrict__ W2,
                const float* __restrict__ b2,
                float* __restrict__ out)
{
    __shared__ float w1s[H_][EIT + 1];
    __shared__ float b1s[H_][EIT + 1];
    __shared__ float w2m[H_][EIT + 1];
    __shared__ float w2s[H_][EIT + 1];
    __shared__ float b2s[2][EIT];

    const int tid = threadIdx.x;
    const int i0  = blockIdx.x * EIT;
    const int b0  = blockIdx.y * EBT;

    // ---- stage weights, coalesced ----
    {
        const int il = tid >> 5;
        const int k  = tid & 31;
        #pragma unroll
        for (int r = 0; r < 4; ++r) {
            const int i = il + r * 8;
            w1s[k][i] = W1[(i0 + i) * H_ + k];
            b1s[k][i] = b1[(i0 + i) * H_ + k];
        }
        const int il2 = tid >> 6;
        const int o   = tid & 63;
        #pragma unroll
        for (int r = 0; r < 8; ++r) {
            const int i = il2 + r * 4;
            float v = W2[(i0 + i) * 2 * H_ + o];
            if (o < H_) w2m[o][i] = v;
            else        w2s[o - H_][i] = v;
        }
        if (tid < 2 * EIT) {
            const int i = tid >> 1;
            b2s[tid & 1][i] = b2[(i0 + i) * 2 + (tid & 1)];
        }
    }
    __syncthreads();

    const int il = tid & 31;
    const int bq = tid >> 5;
    const int gi = i0 + il;
    const int b  = b0 + bq;

    float c = 0.f;
    #pragma unroll
    for (int s = 0; s < SPLITK; ++s)
        c += g_part[s][(size_t)b * N_ + gi];

    float m  = b2s[0][il];
    float sd = b2s[1][il];
    #pragma unroll
    for (int k = 0; k < H_; ++k) {
        float h = fmaxf(fmaf(c, w1s[k][il], b1s[k][il]), 0.f);
        m  = fmaf(w2m[k][il], h, m);
        sd = fmaf(w2s[k][il], h, sd);
    }
    out[(size_t)b * N_ + gi]        = m;
    out[(size_t)(B_ + b) * N_ + gi] = sd;
}

extern "C" void kernel_launch(void* const* d_in, const int* in_sizes, int n_in,
                              void* d_out, int out_size)
{
    const float* x    = (const float*)d_in[0];
    const float* adj  = (const float*)d_in[1];
    const float* bp   = (const float*)d_in[2];
    const float* w_pw = (const float*)d_in[3];
    const float* b_pw = (const float*)d_in[4];
    const float* W1   = (const float*)d_in[5];
    const float* b1   = (const float*)d_in[6];
    const float* W2   = (const float*)d_in[7];
    const float* b2   = (const float*)d_in[8];
    float* out = (float*)d_out;

    gemm_fused<<<dim3(4, 4, SPLITK), 256>>>(x, adj, bp, w_pw, b_pw);
    epi_kernel<<<dim3(N_ / EIT, B_ / EBT), 256>>>(W1, b1, W2, b2, out);
}